// round 1
// baseline (speedup 1.0000x reference)
#include <cuda_runtime.h>
#include <cuda_bf16.h>
#include <mma.h>
#include <cstdint>

using namespace nvcuda;

// Problem sizes (fixed by the reference)
#define NROWS 8192
#define DDIM  512

// ---------------- device scratch (allocation-free rule: __device__ globals) ----
__device__ __nv_bfloat16 g_Hb[(size_t)NROWS * DDIM];
__device__ __nv_bfloat16 g_Qb[(size_t)NROWS * DDIM];
__device__ __nv_bfloat16 g_Kb[(size_t)NROWS * DDIM];
__device__ __nv_bfloat16 g_P [(size_t)NROWS * NROWS];   // 128 MB, exp(scores)
__device__ float         g_rowsum[NROWS];

// ---------------- kernel 0: convert H to bf16, zero row sums --------------------
__global__ __launch_bounds__(256) void prep_kernel(const float* __restrict__ H) {
    int idx = blockIdx.x * blockDim.x + threadIdx.x;       // 0 .. 8192*512/4-1
    float4 v = reinterpret_cast<const float4*>(H)[idx];
    __nv_bfloat162 lo = __floats2bfloat162_rn(v.x, v.y);
    __nv_bfloat162 hi = __floats2bfloat162_rn(v.z, v.w);
    reinterpret_cast<__nv_bfloat162*>(g_Hb)[idx * 2 + 0] = lo;
    reinterpret_cast<__nv_bfloat162*>(g_Hb)[idx * 2 + 1] = hi;
    if (idx < NROWS) g_rowsum[idx] = 0.0f;
}

// ---------------- shared tile loaders -------------------------------------------
// 128x32 bf16 tile, source row-major with leading dim `ld`, smem ld = 40
__device__ __forceinline__ void load_tile_128x32(
    __nv_bfloat16* smem, const __nv_bfloat16* __restrict__ src,
    int row0, int col0, int ld)
{
    int t = threadIdx.x;
#pragma unroll
    for (int r = 0; r < 4; ++r) {
        int chunk = t + r * 256;          // 0..1023
        int row = chunk >> 3;             // 128 rows
        int c4  = (chunk & 7) << 2;       // 8 x 4 cols
        uint64_t v = *reinterpret_cast<const uint64_t*>(
            src + (size_t)(row0 + row) * ld + col0 + c4);
        *reinterpret_cast<uint64_t*>(smem + row * 40 + c4) = v;
    }
}

// 32x128 bf16 tile, source row-major, smem ld = 136
__device__ __forceinline__ void load_tile_32x128_bf16(
    __nv_bfloat16* smem, const __nv_bfloat16* __restrict__ src,
    int row0, int col0, int ld)
{
    int t = threadIdx.x;
#pragma unroll
    for (int r = 0; r < 4; ++r) {
        int chunk = t + r * 256;
        int row = chunk >> 5;             // 32 rows
        int c4  = (chunk & 31) << 2;      // 32 x 4 cols
        uint64_t v = *reinterpret_cast<const uint64_t*>(
            src + (size_t)(row0 + row) * ld + col0 + c4);
        *reinterpret_cast<uint64_t*>(smem + row * 136 + c4) = v;
    }
}

// 32x128 fp32 tile converted to bf16, smem ld = 136
__device__ __forceinline__ void load_tile_32x128_f32(
    __nv_bfloat16* smem, const float* __restrict__ src,
    int row0, int col0, int ld)
{
    int t = threadIdx.x;
#pragma unroll
    for (int r = 0; r < 4; ++r) {
        int chunk = t + r * 256;
        int row = chunk >> 5;
        int c4  = (chunk & 31) << 2;
        float4 v = *reinterpret_cast<const float4*>(
            src + (size_t)(row0 + row) * ld + col0 + c4);
        __nv_bfloat162 lo = __floats2bfloat162_rn(v.x, v.y);
        __nv_bfloat162 hi = __floats2bfloat162_rn(v.z, v.w);
        *reinterpret_cast<__nv_bfloat162*>(smem + row * 136 + c4 + 0) = lo;
        *reinterpret_cast<__nv_bfloat162*>(smem + row * 136 + c4 + 2) = hi;
    }
}

// pack 4 floats into 4 bf16 (one 8-byte word)
__device__ __forceinline__ unsigned long long pack4_bf16(float a, float b, float c, float d) {
    __nv_bfloat162 q0 = __floats2bfloat162_rn(a, b);
    __nv_bfloat162 q1 = __floats2bfloat162_rn(c, d);
    unsigned lo = *reinterpret_cast<unsigned*>(&q0);
    unsigned hi = *reinterpret_cast<unsigned*>(&q1);
    return ((unsigned long long)hi << 32) | lo;
}

// ---------------- kernel 1: Q/K projection --------------------------------------
// C[8192,512] = Hb @ W (+bias), W fp32. blockIdx.z: 0 -> Q, 1 -> K.
// Block tile 128x128, 8 warps (4 M x 2 N), warp tile 32x64.
__global__ __launch_bounds__(256) void proj_kernel(
    const float* __restrict__ Wq, const float* __restrict__ bq,
    const float* __restrict__ Wk, const float* __restrict__ bk)
{
    __shared__ __align__(16) char sm[33536];
    __nv_bfloat16* As = reinterpret_cast<__nv_bfloat16*>(sm);            // 128x40
    __nv_bfloat16* Bs = reinterpret_cast<__nv_bfloat16*>(sm + 10240);    // 32x136
    float*         Cs = reinterpret_cast<float*>(sm);                    // 128x64

    const float* W    = blockIdx.z ? Wk : Wq;
    const float* bias = blockIdx.z ? bk : bq;
    __nv_bfloat16* Out = blockIdx.z ? g_Kb : g_Qb;

    int bm = blockIdx.y;            // 0..63
    int bn = blockIdx.x;            // 0..3
    int wid = threadIdx.x >> 5;
    int warp_m = wid & 3;
    int warp_n = wid >> 2;

    wmma::fragment<wmma::accumulator, 16, 16, 16, float> acc[2][4];
#pragma unroll
    for (int i = 0; i < 2; ++i)
#pragma unroll
        for (int j = 0; j < 4; ++j) wmma::fill_fragment(acc[i][j], 0.0f);

    for (int k0 = 0; k0 < DDIM; k0 += 32) {
        load_tile_128x32(As, g_Hb, bm * 128, k0, DDIM);
        load_tile_32x128_f32(Bs, W, k0, bn * 128, DDIM);
        __syncthreads();
#pragma unroll
        for (int kk = 0; kk < 2; ++kk) {
            wmma::fragment<wmma::matrix_a, 16, 16, 16, __nv_bfloat16, wmma::row_major> af[2];
            wmma::fragment<wmma::matrix_b, 16, 16, 16, __nv_bfloat16, wmma::row_major> bf[4];
#pragma unroll
            for (int i = 0; i < 2; ++i)
                wmma::load_matrix_sync(af[i], As + (warp_m * 32 + i * 16) * 40 + kk * 16, 40);
#pragma unroll
            for (int j = 0; j < 4; ++j)
                wmma::load_matrix_sync(bf[j], Bs + (kk * 16) * 136 + warp_n * 64 + j * 16, 136);
#pragma unroll
            for (int i = 0; i < 2; ++i)
#pragma unroll
                for (int j = 0; j < 4; ++j)
                    wmma::mma_sync(acc[i][j], af[i], bf[j], acc[i][j]);
        }
        __syncthreads();
    }

    // epilogue in two 128x64 halves through smem
    for (int h = 0; h < 2; ++h) {
        if (warp_n == h) {
#pragma unroll
            for (int i = 0; i < 2; ++i)
#pragma unroll
                for (int j = 0; j < 4; ++j)
                    wmma::store_matrix_sync(Cs + (warp_m * 32 + i * 16) * 64 + j * 16,
                                            acc[i][j], 64, wmma::mem_row_major);
        }
        __syncthreads();
        int t = threadIdx.x;
        int cv = (t & 15) << 2;
        float4 bv = *reinterpret_cast<const float4*>(bias + bn * 128 + h * 64 + cv);
#pragma unroll
        for (int i = 0; i < 8; ++i) {
            int vid = i * 256 + t;
            int row = vid >> 4;
            int gr  = bm * 128 + row;
            int gc0 = bn * 128 + h * 64 + cv;
            float v0 = Cs[row * 64 + cv + 0] + bv.x;
            float v1 = Cs[row * 64 + cv + 1] + bv.y;
            float v2 = Cs[row * 64 + cv + 2] + bv.z;
            float v3 = Cs[row * 64 + cv + 3] + bv.w;
            *reinterpret_cast<unsigned long long*>(Out + (size_t)gr * DDIM + gc0) =
                pack4_bf16(v0, v1, v2, v3);
        }
        __syncthreads();
    }
}

// ---------------- kernel 2: scores P = exp(mask(Q K^T)/sqrt(D)), row sums -------
__global__ __launch_bounds__(256) void scores_kernel() {
    __shared__ __align__(16) char sm[33536];
    __nv_bfloat16* As = reinterpret_cast<__nv_bfloat16*>(sm);           // Q tile 128x40
    __nv_bfloat16* Ks = reinterpret_cast<__nv_bfloat16*>(sm + 10240);   // K tile 128x40 (n-major)
    float*         Cs = reinterpret_cast<float*>(sm);                   // 128x64
    float*         srow = reinterpret_cast<float*>(sm + 32768);         // 128 row partials

    int bm = blockIdx.y;            // 0..63 (query rows)
    int bn = blockIdx.x;            // 0..63 (key rows)
    int wid = threadIdx.x >> 5;
    int warp_m = wid & 3;
    int warp_n = wid >> 2;

    wmma::fragment<wmma::accumulator, 16, 16, 16, float> acc[2][4];
#pragma unroll
    for (int i = 0; i < 2; ++i)
#pragma unroll
        for (int j = 0; j < 4; ++j) wmma::fill_fragment(acc[i][j], 0.0f);

    for (int k0 = 0; k0 < DDIM; k0 += 32) {
        load_tile_128x32(As, g_Qb, bm * 128, k0, DDIM);
        load_tile_128x32(Ks, g_Kb, bn * 128, k0, DDIM);   // rows = key index n, cols = k
        __syncthreads();
#pragma unroll
        for (int kk = 0; kk < 2; ++kk) {
            wmma::fragment<wmma::matrix_a, 16, 16, 16, __nv_bfloat16, wmma::row_major> af[2];
            wmma::fragment<wmma::matrix_b, 16, 16, 16, __nv_bfloat16, wmma::col_major> bf[4];
#pragma unroll
            for (int i = 0; i < 2; ++i)
                wmma::load_matrix_sync(af[i], As + (warp_m * 32 + i * 16) * 40 + kk * 16, 40);
#pragma unroll
            for (int j = 0; j < 4; ++j)
                wmma::load_matrix_sync(bf[j], Ks + (warp_n * 64 + j * 16) * 40 + kk * 16, 40);
#pragma unroll
            for (int i = 0; i < 2; ++i)
#pragma unroll
                for (int j = 0; j < 4; ++j)
                    wmma::mma_sync(acc[i][j], af[i], bf[j], acc[i][j]);
        }
        __syncthreads();
    }

    if (threadIdx.x < 128) srow[threadIdx.x] = 0.0f;
    __syncthreads();

    const float scale = 0.044194173824159216f;   // 1/sqrt(512)
    for (int h = 0; h < 2; ++h) {
        if (warp_n == h) {
#pragma unroll
            for (int i = 0; i < 2; ++i)
#pragma unroll
                for (int j = 0; j < 4; ++j)
                    wmma::store_matrix_sync(Cs + (warp_m * 32 + i * 16) * 64 + j * 16,
                                            acc[i][j], 64, wmma::mem_row_major);
        }
        __syncthreads();
        int t = threadIdx.x;
#pragma unroll
        for (int i = 0; i < 8; ++i) {
            int vid = i * 256 + t;
            int row = vid >> 4;
            int cv  = (vid & 15) << 2;
            int gr  = bm * 128 + row;
            int gc0 = bn * 128 + h * 64 + cv;
            float p[4];
#pragma unroll
            for (int u = 0; u < 4; ++u) {
                float v = Cs[row * 64 + cv + u];
                int gc = gc0 + u;
                // reference zeros the diagonal BEFORE scale+softmax -> exp(0)=1
                p[u] = (gr == gc) ? 1.0f : __expf(v * scale);
            }
            *reinterpret_cast<unsigned long long*>(g_P + (size_t)gr * NROWS + gc0) =
                pack4_bf16(p[0], p[1], p[2], p[3]);
            float s = p[0] + p[1] + p[2] + p[3];
#pragma unroll
            for (int m = 1; m < 16; m <<= 1)
                s += __shfl_xor_sync(0xffffffffu, s, m);
            if ((t & 15) == 0) atomicAdd(&srow[row], s);
        }
        __syncthreads();
    }
    if (threadIdx.x < 128)
        atomicAdd(&g_rowsum[bm * 128 + threadIdx.x], srow[threadIdx.x]);
}

// ---------------- kernel 3: O = (P @ H)/rowsum + H ------------------------------
__global__ __launch_bounds__(256) void out_kernel(
    const float* __restrict__ H, float* __restrict__ Out)
{
    __shared__ __align__(16) char sm[33536];
    __nv_bfloat16* As = reinterpret_cast<__nv_bfloat16*>(sm);            // P tile 128x40
    __nv_bfloat16* Bs = reinterpret_cast<__nv_bfloat16*>(sm + 10240);    // H tile 32x136
    float*         Cs = reinterpret_cast<float*>(sm);                    // 128x64

    int bm = blockIdx.y;            // 0..63
    int bn = blockIdx.x;            // 0..3
    int wid = threadIdx.x >> 5;
    int warp_m = wid & 3;
    int warp_n = wid >> 2;

    wmma::fragment<wmma::accumulator, 16, 16, 16, float> acc[2][4];
#pragma unroll
    for (int i = 0; i < 2; ++i)
#pragma unroll
        for (int j = 0; j < 4; ++j) wmma::fill_fragment(acc[i][j], 0.0f);

    for (int k0 = 0; k0 < NROWS; k0 += 32) {
        load_tile_128x32(As, g_P, bm * 128, k0, NROWS);
        load_tile_32x128_bf16(Bs, g_Hb, k0, bn * 128, DDIM);
        __syncthreads();
#pragma unroll
        for (int kk = 0; kk < 2; ++kk) {
            wmma::fragment<wmma::matrix_a, 16, 16, 16, __nv_bfloat16, wmma::row_major> af[2];
            wmma::fragment<wmma::matrix_b, 16, 16, 16, __nv_bfloat16, wmma::row_major> bf[4];
#pragma unroll
            for (int i = 0; i < 2; ++i)
                wmma::load_matrix_sync(af[i], As + (warp_m * 32 + i * 16) * 40 + kk * 16, 40);
#pragma unroll
            for (int j = 0; j < 4; ++j)
                wmma::load_matrix_sync(bf[j], Bs + (kk * 16) * 136 + warp_n * 64 + j * 16, 136);
#pragma unroll
            for (int i = 0; i < 2; ++i)
#pragma unroll
                for (int j = 0; j < 4; ++j)
                    wmma::mma_sync(acc[i][j], af[i], bf[j], acc[i][j]);
        }
        __syncthreads();
    }

    for (int h = 0; h < 2; ++h) {
        if (warp_n == h) {
#pragma unroll
            for (int i = 0; i < 2; ++i)
#pragma unroll
                for (int j = 0; j < 4; ++j)
                    wmma::store_matrix_sync(Cs + (warp_m * 32 + i * 16) * 64 + j * 16,
                                            acc[i][j], 64, wmma::mem_row_major);
        }
        __syncthreads();
        int t = threadIdx.x;
#pragma unroll
        for (int i = 0; i < 8; ++i) {
            int vid = i * 256 + t;
            int row = vid >> 4;
            int cv  = (vid & 15) << 2;
            int gr  = bm * 128 + row;
            int gc0 = bn * 128 + h * 64 + cv;
            float rinv = 1.0f / g_rowsum[gr];
            float4 hv = *reinterpret_cast<const float4*>(H + (size_t)gr * DDIM + gc0);
            float4 o;
            o.x = Cs[row * 64 + cv + 0] * rinv + hv.x;
            o.y = Cs[row * 64 + cv + 1] * rinv + hv.y;
            o.z = Cs[row * 64 + cv + 2] * rinv + hv.z;
            o.w = Cs[row * 64 + cv + 3] * rinv + hv.w;
            *reinterpret_cast<float4*>(Out + (size_t)gr * DDIM + gc0) = o;
        }
        __syncthreads();
    }
}

// ---------------- launch ---------------------------------------------------------
extern "C" void kernel_launch(void* const* d_in, const int* in_sizes, int n_in,
                              void* d_out, int out_size) {
    const float* H  = (const float*)d_in[0];
    const float* Wq = (const float*)d_in[1];
    const float* bq = (const float*)d_in[2];
    const float* Wk = (const float*)d_in[3];
    const float* bk = (const float*)d_in[4];
    float* out = (float*)d_out;

    prep_kernel<<<(NROWS * DDIM / 4) / 256, 256>>>(H);
    proj_kernel<<<dim3(4, 64, 2), 256>>>(Wq, bq, Wk, bk);
    scores_kernel<<<dim3(64, 64), 256>>>();
    out_kernel<<<dim3(4, 64), 256>>>(H, out);
}

// round 3
// speedup vs baseline: 1.6921x; 1.6921x over previous
#include <cuda_runtime.h>
#include <cuda_bf16.h>
#include <cstdint>

// ------------------------------------------------------------------ sizes
#define NROWS 8192
#define DDIM  512

// ------------------------------------------------------------ device scratch
__device__ __nv_bfloat16 g_Hb [(size_t)NROWS * DDIM];   // H bf16 row-major
__device__ __nv_bfloat16 g_HbT[(size_t)DDIM * NROWS];   // H^T bf16 [512][8192]
__device__ __nv_bfloat16 g_WqT[(size_t)DDIM * DDIM];    // Wq^T bf16
__device__ __nv_bfloat16 g_WkT[(size_t)DDIM * DDIM];
__device__ __nv_bfloat16 g_Qb [(size_t)NROWS * DDIM];
__device__ __nv_bfloat16 g_Kb [(size_t)NROWS * DDIM];
__device__ __nv_bfloat16 g_P  [(size_t)NROWS * NROWS];  // 128 MB exp(scores)
__device__ float         g_rowsum[NROWS];

// ------------------------------------------------------------ PTX helpers
__device__ __forceinline__ uint32_t smem_u32(const void* p) {
    uint32_t a;
    asm("{ .reg .u64 t; cvta.to.shared.u64 t, %1; cvt.u32.u64 %0, t; }"
        : "=r"(a) : "l"(p));
    return a;
}
__device__ __forceinline__ void cp_async16(uint32_t dst, const void* src) {
    asm volatile("cp.async.cg.shared.global [%0], [%1], 16;"
                 :: "r"(dst), "l"(src) : "memory");
}
__device__ __forceinline__ void cp_commit() {
    asm volatile("cp.async.commit_group;" ::: "memory");
}
template<int N> __device__ __forceinline__ void cp_wait() {
    asm volatile("cp.async.wait_group %0;" :: "n"(N) : "memory");
}
__device__ __forceinline__ void ldsm_x4(uint32_t& r0, uint32_t& r1,
                                        uint32_t& r2, uint32_t& r3, uint32_t addr) {
    asm volatile("ldmatrix.sync.aligned.m8n8.x4.shared.b16 {%0,%1,%2,%3}, [%4];"
                 : "=r"(r0), "=r"(r1), "=r"(r2), "=r"(r3) : "r"(addr));
}
__device__ __forceinline__ void mma16816(float* c, const uint32_t* a,
                                         uint32_t b0, uint32_t b1) {
    asm volatile(
        "mma.sync.aligned.m16n8k16.row.col.f32.bf16.bf16.f32 "
        "{%0,%1,%2,%3}, {%4,%5,%6,%7}, {%8,%9}, {%0,%1,%2,%3};"
        : "+f"(c[0]), "+f"(c[1]), "+f"(c[2]), "+f"(c[3])
        : "r"(a[0]), "r"(a[1]), "r"(a[2]), "r"(a[3]), "r"(b0), "r"(b1));
}
// XOR-swizzled smem addr: 64 bf16 per row (128B), 16B granularity
__device__ __forceinline__ uint32_t sw(uint32_t base, int row, int c16) {
    return base + row * 128 + (((uint32_t)c16 ^ (row & 7)) << 4);
}

// ------------------------------------------------------------ prep kernels
__global__ __launch_bounds__(256) void prep_kernel(const float* __restrict__ H) {
    int idx = blockIdx.x * blockDim.x + threadIdx.x;
    float4 v = reinterpret_cast<const float4*>(H)[idx];
    __nv_bfloat162 lo = __floats2bfloat162_rn(v.x, v.y);
    __nv_bfloat162 hi = __floats2bfloat162_rn(v.z, v.w);
    reinterpret_cast<__nv_bfloat162*>(g_Hb)[idx * 2 + 0] = lo;
    reinterpret_cast<__nv_bfloat162*>(g_Hb)[idx * 2 + 1] = hi;
    if (idx < NROWS) g_rowsum[idx] = 0.0f;
}

// in fp32 [R][C] -> out bf16 [C][R]
__global__ __launch_bounds__(256) void transpose_kernel(
    const float* __restrict__ in, __nv_bfloat16* __restrict__ out, int R, int C)
{
    __shared__ float tile[32][33];
    int bx = blockIdx.x * 32, by = blockIdx.y * 32;
    int tx = threadIdx.x, ty = threadIdx.y;
#pragma unroll
    for (int i = 0; i < 32; i += 8)
        tile[ty + i][tx] = in[(size_t)(by + ty + i) * C + bx + tx];
    __syncthreads();
#pragma unroll
    for (int i = 0; i < 32; i += 8)
        out[(size_t)(bx + ty + i) * R + by + tx] = __float2bfloat16(tile[tx][ty + i]);
}

// ------------------------------------------------------------ HMMA GEMM
// D = A @ B^T. A [M,K] K-major (lda), B [N,K] K-major (ldb).
// CTA tile 128x128, 8 warps (4 M x 2 N), warp tile 32x64, K chunk 64.
// MODE 0: out bf16 = D + bias (Aux=bias)     ld=DDIM
// MODE 1: out bf16 P = exp(mask(D)/s), rowsum atomics     ld=NROWS
// MODE 2: out fp32 = D / rowsum + H (Aux=H)  ld=DDIM
#define STAGES   4
#define STAGE_SZ 32768          // A 16KB + B 16KB
#define SMEM_DYN (STAGES * STAGE_SZ)

__device__ __forceinline__ void load_chunk(
    const __nv_bfloat16* __restrict__ A, int lda,
    const __nv_bfloat16* __restrict__ B, int ldb,
    int arow0, int brow0, int kbase, uint32_t stage)
{
    int t = threadIdx.x;
#pragma unroll
    for (int i = 0; i < 4; ++i) {
        int gid = i * 256 + t;
        int row = gid >> 3, c16 = gid & 7;
        cp_async16(sw(stage, row, c16),
                   A + (size_t)(arow0 + row) * lda + kbase + c16 * 8);
    }
#pragma unroll
    for (int i = 0; i < 4; ++i) {
        int gid = i * 256 + t;
        int row = gid >> 3, c16 = gid & 7;
        cp_async16(sw(stage + 16384, row, c16),
                   B + (size_t)(brow0 + row) * ldb + kbase + c16 * 8);
    }
    cp_commit();
}

template<int KC, int MODE>
__global__ __launch_bounds__(256, 1) void gemm_kernel(
    const __nv_bfloat16* __restrict__ A, int lda,
    const __nv_bfloat16* __restrict__ B, int ldb,
    void* __restrict__ Out, const float* __restrict__ Aux)
{
    extern __shared__ __align__(128) char sm[];
    __shared__ float srow[128];
    const uint32_t smb = smem_u32(sm);
    const int t = threadIdx.x, lane = t & 31, wid = t >> 5;
    const int wm = wid & 3, wn = wid >> 2;        // 4 x 2 warp grid
    const int bn = blockIdx.x, bm = blockIdx.y;
    const int m0 = wm * 32, n0 = wn * 64;

    if (MODE == 1 && t < 128) srow[t] = 0.0f;

    float acc[2][8][4] = {};

    // prologue: stages 0..2 (KC >= 8 always)
#pragma unroll
    for (int c = 0; c < STAGES - 1; ++c)
        load_chunk(A, lda, B, ldb, bm * 128, bn * 128, c * 64, smb + c * STAGE_SZ);

    for (int c = 0; c < KC; ++c) {
        // complete chunk c
        if (c + 2 <= KC - 1)      cp_wait<2>();
        else if (c + 1 <= KC - 1) cp_wait<1>();
        else                      cp_wait<0>();
        __syncthreads();
        // refill the stage freed by chunk c-1 with chunk c+3
        if (c + STAGES - 1 < KC)
            load_chunk(A, lda, B, ldb, bm * 128, bn * 128, (c + 3) * 64,
                       smb + ((c + 3) & 3) * STAGE_SZ);

        const uint32_t sA = smb + (c & 3) * STAGE_SZ;
        const uint32_t sB = sA + 16384;
#pragma unroll
        for (int ks = 0; ks < 4; ++ks) {
            const int k16 = ks * 2;   // c16 base
            uint32_t a[2][4];
#pragma unroll
            for (int i = 0; i < 2; ++i) {
                int row = m0 + i * 16 + (lane & 15);
                ldsm_x4(a[i][0], a[i][1], a[i][2], a[i][3],
                        sw(sA, row, k16 + (lane >> 4)));
            }
            uint32_t b[4][4];
#pragma unroll
            for (int g = 0; g < 4; ++g) {
                int row = n0 + g * 16 + (lane & 7) + ((lane >> 4) << 3);
                ldsm_x4(b[g][0], b[g][1], b[g][2], b[g][3],
                        sw(sB, row, k16 + ((lane >> 3) & 1)));
            }
#pragma unroll
            for (int i = 0; i < 2; ++i)
#pragma unroll
                for (int j = 0; j < 8; ++j)
                    mma16816(acc[i][j], a[i], b[j >> 1][(j & 1) * 2],
                             b[j >> 1][(j & 1) * 2 + 1]);
        }
    }

    // ------------------------------------------------------------ epilogue
    const float SCALE = 0.044194173824159216f;    // 1/sqrt(512)
    const int rq = lane >> 2, cq = (lane & 3) * 2;

    if (MODE == 1) {
        __nv_bfloat16* P = (__nv_bfloat16*)Out;
        float rs[2][2] = {};
#pragma unroll
        for (int i = 0; i < 2; ++i) {
            int gr0 = bm * 128 + m0 + i * 16 + rq;
#pragma unroll
            for (int j = 0; j < 8; ++j) {
                int gc = bn * 128 + n0 + j * 8 + cq;
                float p0 = (gr0 == gc)         ? 1.0f : __expf(acc[i][j][0] * SCALE);
                float p1 = (gr0 == gc + 1)     ? 1.0f : __expf(acc[i][j][1] * SCALE);
                float p2 = (gr0 + 8 == gc)     ? 1.0f : __expf(acc[i][j][2] * SCALE);
                float p3 = (gr0 + 8 == gc + 1) ? 1.0f : __expf(acc[i][j][3] * SCALE);
                rs[i][0] += p0 + p1;
                rs[i][1] += p2 + p3;
                __nv_bfloat162 h0 = __floats2bfloat162_rn(p0, p1);
                __nv_bfloat162 h1 = __floats2bfloat162_rn(p2, p3);
                *(__nv_bfloat162*)(P + (size_t)gr0 * NROWS + gc)       = h0;
                *(__nv_bfloat162*)(P + (size_t)(gr0 + 8) * NROWS + gc) = h1;
            }
        }
#pragma unroll
        for (int i = 0; i < 2; ++i)
#pragma unroll
            for (int h = 0; h < 2; ++h) {
                float v = rs[i][h];
                v += __shfl_xor_sync(0xffffffffu, v, 1);
                v += __shfl_xor_sync(0xffffffffu, v, 2);
                if ((lane & 3) == 0)
                    atomicAdd(&srow[m0 + i * 16 + h * 8 + rq], v);
            }
        __syncthreads();
        if (t < 128) atomicAdd(&g_rowsum[bm * 128 + t], srow[t]);
    } else if (MODE == 0) {
        __nv_bfloat16* O = (__nv_bfloat16*)Out;
#pragma unroll
        for (int i = 0; i < 2; ++i) {
            int gr0 = bm * 128 + m0 + i * 16 + rq;
#pragma unroll
            for (int j = 0; j < 8; ++j) {
                int gc = bn * 128 + n0 + j * 8 + cq;
                float2 bv = *(const float2*)(Aux + gc);
                __nv_bfloat162 h0 = __floats2bfloat162_rn(acc[i][j][0] + bv.x,
                                                          acc[i][j][1] + bv.y);
                __nv_bfloat162 h1 = __floats2bfloat162_rn(acc[i][j][2] + bv.x,
                                                          acc[i][j][3] + bv.y);
                *(__nv_bfloat162*)(O + (size_t)gr0 * DDIM + gc)       = h0;
                *(__nv_bfloat162*)(O + (size_t)(gr0 + 8) * DDIM + gc) = h1;
            }
        }
    } else {   // MODE 2
        float* O = (float*)Out;
#pragma unroll
        for (int i = 0; i < 2; ++i) {
            int gr0 = bm * 128 + m0 + i * 16 + rq;
            float rinv0 = 1.0f / __ldg(&g_rowsum[gr0]);
            float rinv1 = 1.0f / __ldg(&g_rowsum[gr0 + 8]);
            const float* H0 = Aux + (size_t)gr0 * DDIM;
            const float* H1 = Aux + (size_t)(gr0 + 8) * DDIM;
#pragma unroll
            for (int j = 0; j < 8; ++j) {
                int gc = bn * 128 + n0 + j * 8 + cq;
                float2 h0 = *(const float2*)(H0 + gc);
                float2 h1 = *(const float2*)(H1 + gc);
                float2 o0 = { acc[i][j][0] * rinv0 + h0.x,
                              acc[i][j][1] * rinv0 + h0.y };
                float2 o1 = { acc[i][j][2] * rinv1 + h1.x,
                              acc[i][j][3] * rinv1 + h1.y };
                *(float2*)(O + (size_t)gr0 * DDIM + gc)       = o0;
                *(float2*)(O + (size_t)(gr0 + 8) * DDIM + gc) = o1;
            }
        }
    }
}

// ------------------------------------------------------------ launch
extern "C" void kernel_launch(void* const* d_in, const int* in_sizes, int n_in,
                              void* d_out, int out_size) {
    const float* H  = (const float*)d_in[0];
    const float* Wq = (const float*)d_in[1];
    const float* bq = (const float*)d_in[2];
    const float* Wk = (const float*)d_in[3];
    const float* bk = (const float*)d_in[4];
    float* out = (float*)d_out;

    void *pHb, *pHbT, *pWqT, *pWkT, *pQb, *pKb, *pP;
    cudaGetSymbolAddress(&pHb,  g_Hb);
    cudaGetSymbolAddress(&pHbT, g_HbT);
    cudaGetSymbolAddress(&pWqT, g_WqT);
    cudaGetSymbolAddress(&pWkT, g_WkT);
    cudaGetSymbolAddress(&pQb,  g_Qb);
    cudaGetSymbolAddress(&pKb,  g_Kb);
    cudaGetSymbolAddress(&pP,   g_P);

    cudaFuncSetAttribute(gemm_kernel<8, 0>,
        cudaFuncAttributeMaxDynamicSharedMemorySize, SMEM_DYN);
    cudaFuncSetAttribute(gemm_kernel<8, 1>,
        cudaFuncAttributeMaxDynamicSharedMemorySize, SMEM_DYN);
    cudaFuncSetAttribute(gemm_kernel<128, 2>,
        cudaFuncAttributeMaxDynamicSharedMemorySize, SMEM_DYN);

    // 1) H -> bf16, rowsums = 0
    prep_kernel<<<(NROWS * DDIM / 4) / 256, 256>>>(H);
    // 2) transposes (fp32 -> bf16)
    transpose_kernel<<<dim3(DDIM / 32, NROWS / 32), dim3(32, 8)>>>(
        H, (__nv_bfloat16*)pHbT, NROWS, DDIM);
    transpose_kernel<<<dim3(DDIM / 32, DDIM / 32), dim3(32, 8)>>>(
        Wq, (__nv_bfloat16*)pWqT, DDIM, DDIM);
    transpose_kernel<<<dim3(DDIM / 32, DDIM / 32), dim3(32, 8)>>>(
        Wk, (__nv_bfloat16*)pWkT, DDIM, DDIM);
    // 3) projections
    gemm_kernel<8, 0><<<dim3(4, 64), 256, SMEM_DYN>>>(
        (const __nv_bfloat16*)pHb, DDIM, (const __nv_bfloat16*)pWqT, DDIM, pQb, bq);
    gemm_kernel<8, 0><<<dim3(4, 64), 256, SMEM_DYN>>>(
        (const __nv_bfloat16*)pHb, DDIM, (const __nv_bfloat16*)pWkT, DDIM, pKb, bk);
    // 4) scores: P = exp(mask(Q K^T)/sqrt(D)), rowsum atomics
    gemm_kernel<8, 1><<<dim3(64, 64), 256, SMEM_DYN>>>(
        (const __nv_bfloat16*)pQb, DDIM, (const __nv_bfloat16*)pKb, DDIM, pP, nullptr);
    // 5) out: O = (P H)/rowsum + H
    gemm_kernel<128, 2><<<dim3(4, 64), 256, SMEM_DYN>>>(
        (const __nv_bfloat16*)pP, NROWS, (const __nv_bfloat16*)pHbT, NROWS, out, H);
}

// round 4
// speedup vs baseline: 1.8999x; 1.1228x over previous
#include <cuda_runtime.h>
#include <cuda_bf16.h>
#include <cstdint>

// ------------------------------------------------------------------ sizes
#define NROWS 8192
#define DDIM  512

// ------------------------------------------------------------ device scratch
__device__ __nv_bfloat16 g_Hb [(size_t)NROWS * DDIM];   // H bf16 row-major
__device__ __nv_bfloat16 g_HbT[(size_t)DDIM * NROWS];   // H^T bf16 [512][8192]
__device__ __nv_bfloat16 g_WqT[(size_t)DDIM * DDIM];    // Wq^T bf16
__device__ __nv_bfloat16 g_WkT[(size_t)DDIM * DDIM];
__device__ __nv_bfloat16 g_Qb [(size_t)NROWS * DDIM];
__device__ __nv_bfloat16 g_Kb [(size_t)NROWS * DDIM];
__device__ __nv_bfloat16 g_P  [(size_t)NROWS * NROWS];  // 128 MB exp(scores)
__device__ float         g_rowsum[NROWS];

// ------------------------------------------------------------ PTX helpers
__device__ __forceinline__ uint32_t smem_u32(const void* p) {
    uint32_t a;
    asm("{ .reg .u64 t; cvta.to.shared.u64 t, %1; cvt.u32.u64 %0, t; }"
        : "=r"(a) : "l"(p));
    return a;
}
__device__ __forceinline__ void cp_async16(uint32_t dst, const void* src) {
    asm volatile("cp.async.cg.shared.global [%0], [%1], 16;"
                 :: "r"(dst), "l"(src) : "memory");
}
__device__ __forceinline__ void cp_commit() {
    asm volatile("cp.async.commit_group;" ::: "memory");
}
template<int N> __device__ __forceinline__ void cp_wait() {
    asm volatile("cp.async.wait_group %0;" :: "n"(N) : "memory");
}
__device__ __forceinline__ void ldsm_x4(uint32_t& r0, uint32_t& r1,
                                        uint32_t& r2, uint32_t& r3, uint32_t addr) {
    asm volatile("ldmatrix.sync.aligned.m8n8.x4.shared.b16 {%0,%1,%2,%3}, [%4];"
                 : "=r"(r0), "=r"(r1), "=r"(r2), "=r"(r3) : "r"(addr));
}
__device__ __forceinline__ void mma16816(float* c, const uint32_t* a,
                                         uint32_t b0, uint32_t b1) {
    asm volatile(
        "mma.sync.aligned.m16n8k16.row.col.f32.bf16.bf16.f32 "
        "{%0,%1,%2,%3}, {%4,%5,%6,%7}, {%8,%9}, {%0,%1,%2,%3};"
        : "+f"(c[0]), "+f"(c[1]), "+f"(c[2]), "+f"(c[3])
        : "r"(a[0]), "r"(a[1]), "r"(a[2]), "r"(a[3]), "r"(b0), "r"(b1));
}
// XOR-swizzled smem addr: 64 bf16 per row (128B), 16B granularity
__device__ __forceinline__ uint32_t sw(uint32_t base, int row, int c16) {
    return base + row * 128 + (((uint32_t)c16 ^ (row & 7)) << 4);
}

// ------------------------------------------------------------ prep kernels
__global__ __launch_bounds__(256) void prep_kernel(const float* __restrict__ H) {
    int idx = blockIdx.x * blockDim.x + threadIdx.x;
    float4 v = reinterpret_cast<const float4*>(H)[idx];
    __nv_bfloat162 lo = __floats2bfloat162_rn(v.x, v.y);
    __nv_bfloat162 hi = __floats2bfloat162_rn(v.z, v.w);
    reinterpret_cast<__nv_bfloat162*>(g_Hb)[idx * 2 + 0] = lo;
    reinterpret_cast<__nv_bfloat162*>(g_Hb)[idx * 2 + 1] = hi;
    if (idx < NROWS) g_rowsum[idx] = 0.0f;
}

// in fp32 [R][C] -> out bf16 [C][R]
__global__ __launch_bounds__(256) void transpose_kernel(
    const float* __restrict__ in, __nv_bfloat16* __restrict__ out, int R, int C)
{
    __shared__ float tile[32][33];
    int bx = blockIdx.x * 32, by = blockIdx.y * 32;
    int tx = threadIdx.x, ty = threadIdx.y;
#pragma unroll
    for (int i = 0; i < 32; i += 8)
        tile[ty + i][tx] = in[(size_t)(by + ty + i) * C + bx + tx];
    __syncthreads();
#pragma unroll
    for (int i = 0; i < 32; i += 8)
        out[(size_t)(bx + ty + i) * R + by + tx] = __float2bfloat16(tile[tx][ty + i]);
}

// ------------------------------------------------------------ HMMA GEMM
// D = A @ B^T. A [M,K] K-major (lda), B [N,K] K-major (ldb).
// CTA tile 128x256, 8 warps (2 M x 4 N), warp tile 64x64, K chunk 64.
// MODE 0: out bf16 = D + bias (Aux=bias)
// MODE 1: out bf16 P = exp(mask(D)/s), rowsum atomics
// MODE 2: out fp32 = D / rowsum + H (Aux=H)
#define STAGES   4
#define STAGE_SZ 49152          // A 16KB + B 32KB
#define SMEM_DYN (STAGES * STAGE_SZ)

__device__ __forceinline__ void load_chunk(
    const __nv_bfloat16* __restrict__ A, int lda,
    const __nv_bfloat16* __restrict__ B, int ldb,
    int arow0, int brow0, int kbase, uint32_t stage)
{
    int t = threadIdx.x;
#pragma unroll
    for (int i = 0; i < 4; ++i) {       // A: 128 rows x 8 c16
        int gid = i * 256 + t;
        int row = gid >> 3, c16 = gid & 7;
        cp_async16(sw(stage, row, c16),
                   A + (size_t)(arow0 + row) * lda + kbase + c16 * 8);
    }
#pragma unroll
    for (int i = 0; i < 8; ++i) {       // B: 256 rows x 8 c16
        int gid = i * 256 + t;
        int row = gid >> 3, c16 = gid & 7;
        cp_async16(sw(stage + 16384, row, c16),
                   B + (size_t)(brow0 + row) * ldb + kbase + c16 * 8);
    }
    cp_commit();
}

template<int KC, int MODE>
__global__ __launch_bounds__(256, 1) void gemm_kernel(
    const __nv_bfloat16* __restrict__ A, int lda,
    const __nv_bfloat16* __restrict__ B, int ldb,
    void* __restrict__ Out, const float* __restrict__ Aux)
{
    extern __shared__ __align__(128) char sm[];
    __shared__ float srow[128];
    const uint32_t smb = smem_u32(sm);
    const int t = threadIdx.x, lane = t & 31, wid = t >> 5;
    const int wm = wid & 1, wn = wid >> 1;        // 2 x 4 warp grid
    const int bn = blockIdx.x, bm = blockIdx.y;
    const int m0 = wm * 64, n0 = wn * 64;

    if (MODE == 1 && t < 128) srow[t] = 0.0f;

    float acc[4][8][4] = {};

    // prologue
#pragma unroll
    for (int c = 0; c < STAGES - 1; ++c)
        load_chunk(A, lda, B, ldb, bm * 128, bn * 256, c * 64, smb + c * STAGE_SZ);

    for (int c = 0; c < KC; ++c) {
        if (c + 2 <= KC - 1)      cp_wait<2>();
        else if (c + 1 <= KC - 1) cp_wait<1>();
        else                      cp_wait<0>();
        __syncthreads();
        if (c + STAGES - 1 < KC)
            load_chunk(A, lda, B, ldb, bm * 128, bn * 256, (c + 3) * 64,
                       smb + ((c + 3) & 3) * STAGE_SZ);

        const uint32_t sA = smb + (c & 3) * STAGE_SZ;
        const uint32_t sB = sA + 16384;
#pragma unroll
        for (int ks = 0; ks < 4; ++ks) {
            const int k16 = ks * 2;
            uint32_t a[4][4];
#pragma unroll
            for (int i = 0; i < 4; ++i) {
                int row = m0 + i * 16 + (lane & 15);
                ldsm_x4(a[i][0], a[i][1], a[i][2], a[i][3],
                        sw(sA, row, k16 + (lane >> 4)));
            }
            uint32_t b[4][4];
#pragma unroll
            for (int g = 0; g < 4; ++g) {
                int row = n0 + g * 16 + (lane & 7) + ((lane >> 4) << 3);
                ldsm_x4(b[g][0], b[g][1], b[g][2], b[g][3],
                        sw(sB, row, k16 + ((lane >> 3) & 1)));
            }
#pragma unroll
            for (int i = 0; i < 4; ++i)
#pragma unroll
                for (int j = 0; j < 8; ++j)
                    mma16816(acc[i][j], a[i], b[j >> 1][(j & 1) * 2],
                             b[j >> 1][(j & 1) * 2 + 1]);
        }
    }

    // ------------------------------------------------------------ epilogue
    // exp(x/sqrt(512)) = exp2(x * log2(e)/sqrt(512))
    const float S2 = 0.06375871566969395f;
    const int rq = lane >> 2, cq = (lane & 3) * 2;

    if (MODE == 1) {
        __nv_bfloat16* P = (__nv_bfloat16*)Out;
        float rs[4][2] = {};
#pragma unroll
        for (int i = 0; i < 4; ++i) {
            int gr0 = bm * 128 + m0 + i * 16 + rq;
#pragma unroll
            for (int j = 0; j < 8; ++j) {
                int gc = bn * 256 + n0 + j * 8 + cq;
                float p0 = (gr0 == gc)         ? 1.0f : exp2f(acc[i][j][0] * S2);
                float p1 = (gr0 == gc + 1)     ? 1.0f : exp2f(acc[i][j][1] * S2);
                float p2 = (gr0 + 8 == gc)     ? 1.0f : exp2f(acc[i][j][2] * S2);
                float p3 = (gr0 + 8 == gc + 1) ? 1.0f : exp2f(acc[i][j][3] * S2);
                rs[i][0] += p0 + p1;
                rs[i][1] += p2 + p3;
                __nv_bfloat162 h0 = __floats2bfloat162_rn(p0, p1);
                __nv_bfloat162 h1 = __floats2bfloat162_rn(p2, p3);
                *(__nv_bfloat162*)(P + (size_t)gr0 * NROWS + gc)       = h0;
                *(__nv_bfloat162*)(P + (size_t)(gr0 + 8) * NROWS + gc) = h1;
            }
        }
#pragma unroll
        for (int i = 0; i < 4; ++i)
#pragma unroll
            for (int h = 0; h < 2; ++h) {
                float v = rs[i][h];
                v += __shfl_xor_sync(0xffffffffu, v, 1);
                v += __shfl_xor_sync(0xffffffffu, v, 2);
                if ((lane & 3) == 0)
                    atomicAdd(&srow[m0 + i * 16 + h * 8 + rq], v);
            }
        __syncthreads();
        if (t < 128) atomicAdd(&g_rowsum[bm * 128 + t], srow[t]);
    } else if (MODE == 0) {
        __nv_bfloat16* O = (__nv_bfloat16*)Out;
#pragma unroll
        for (int i = 0; i < 4; ++i) {
            int gr0 = bm * 128 + m0 + i * 16 + rq;
#pragma unroll
            for (int j = 0; j < 8; ++j) {
                int gc = bn * 256 + n0 + j * 8 + cq;
                float2 bv = *(const float2*)(Aux + gc);
                __nv_bfloat162 h0 = __floats2bfloat162_rn(acc[i][j][0] + bv.x,
                                                          acc[i][j][1] + bv.y);
                __nv_bfloat162 h1 = __floats2bfloat162_rn(acc[i][j][2] + bv.x,
                                                          acc[i][j][3] + bv.y);
                *(__nv_bfloat162*)(O + (size_t)gr0 * DDIM + gc)       = h0;
                *(__nv_bfloat162*)(O + (size_t)(gr0 + 8) * DDIM + gc) = h1;
            }
        }
    } else {   // MODE 2
        float* O = (float*)Out;
#pragma unroll
        for (int i = 0; i < 4; ++i) {
            int gr0 = bm * 128 + m0 + i * 16 + rq;
            float rinv0 = 1.0f / __ldg(&g_rowsum[gr0]);
            float rinv1 = 1.0f / __ldg(&g_rowsum[gr0 + 8]);
            const float* H0 = Aux + (size_t)gr0 * DDIM;
            const float* H1 = Aux + (size_t)(gr0 + 8) * DDIM;
#pragma unroll
            for (int j = 0; j < 8; ++j) {
                int gc = bn * 256 + n0 + j * 8 + cq;
                float2 h0 = *(const float2*)(H0 + gc);
                float2 h1 = *(const float2*)(H1 + gc);
                float2 o0 = { acc[i][j][0] * rinv0 + h0.x,
                              acc[i][j][1] * rinv0 + h0.y };
                float2 o1 = { acc[i][j][2] * rinv1 + h1.x,
                              acc[i][j][3] * rinv1 + h1.y };
                *(float2*)(O + (size_t)gr0 * DDIM + gc)       = o0;
                *(float2*)(O + (size_t)(gr0 + 8) * DDIM + gc) = o1;
            }
        }
    }
}

// ------------------------------------------------------------ launch
extern "C" void kernel_launch(void* const* d_in, const int* in_sizes, int n_in,
                              void* d_out, int out_size) {
    const float* H  = (const float*)d_in[0];
    const float* Wq = (const float*)d_in[1];
    const float* bq = (const float*)d_in[2];
    const float* Wk = (const float*)d_in[3];
    const float* bk = (const float*)d_in[4];
    float* out = (float*)d_out;

    void *pHb, *pHbT, *pWqT, *pWkT, *pQb, *pKb, *pP;
    cudaGetSymbolAddress(&pHb,  g_Hb);
    cudaGetSymbolAddress(&pHbT, g_HbT);
    cudaGetSymbolAddress(&pWqT, g_WqT);
    cudaGetSymbolAddress(&pWkT, g_WkT);
    cudaGetSymbolAddress(&pQb,  g_Qb);
    cudaGetSymbolAddress(&pKb,  g_Kb);
    cudaGetSymbolAddress(&pP,   g_P);

    cudaFuncSetAttribute(gemm_kernel<8, 0>,
        cudaFuncAttributeMaxDynamicSharedMemorySize, SMEM_DYN);
    cudaFuncSetAttribute(gemm_kernel<8, 1>,
        cudaFuncAttributeMaxDynamicSharedMemorySize, SMEM_DYN);
    cudaFuncSetAttribute(gemm_kernel<128, 2>,
        cudaFuncAttributeMaxDynamicSharedMemorySize, SMEM_DYN);

    // 1) H -> bf16, rowsums = 0
    prep_kernel<<<(NROWS * DDIM / 4) / 256, 256>>>(H);
    // 2) transposes (fp32 -> bf16)
    transpose_kernel<<<dim3(DDIM / 32, NROWS / 32), dim3(32, 8)>>>(
        H, (__nv_bfloat16*)pHbT, NROWS, DDIM);
    transpose_kernel<<<dim3(DDIM / 32, DDIM / 32), dim3(32, 8)>>>(
        Wq, (__nv_bfloat16*)pWqT, DDIM, DDIM);
    transpose_kernel<<<dim3(DDIM / 32, DDIM / 32), dim3(32, 8)>>>(
        Wk, (__nv_bfloat16*)pWkT, DDIM, DDIM);
    // 3) projections: CTA 128x256 -> grid (2, 64)
    gemm_kernel<8, 0><<<dim3(2, 64), 256, SMEM_DYN>>>(
        (const __nv_bfloat16*)pHb, DDIM, (const __nv_bfloat16*)pWqT, DDIM, pQb, bq);
    gemm_kernel<8, 0><<<dim3(2, 64), 256, SMEM_DYN>>>(
        (const __nv_bfloat16*)pHb, DDIM, (const __nv_bfloat16*)pWkT, DDIM, pKb, bk);
    // 4) scores: grid (32, 64)
    gemm_kernel<8, 1><<<dim3(32, 64), 256, SMEM_DYN>>>(
        (const __nv_bfloat16*)pQb, DDIM, (const __nv_bfloat16*)pKb, DDIM, pP, nullptr);
    // 5) out: grid (2, 64)
    gemm_kernel<128, 2><<<dim3(2, 64), 256, SMEM_DYN>>>(
        (const __nv_bfloat16*)pP, NROWS, (const __nv_bfloat16*)pHbT, NROWS, out, H);
}